// round 3
// baseline (speedup 1.0000x reference)
#include <cuda_runtime.h>
#include <math.h>
#include <stdint.h>

#define NN 8
#define CC 1024
#define BB 2048
#define EPS 1e-12f

// ---- scratch (device globals; no allocation allowed) ----
__device__ float g_K[(size_t)NN * CC * BB];    // 64 MB (tf32-rounded fp32)
__device__ float g_Q[(size_t)NN * CC * BB];    // 64 MB (tf32-rounded fp32)
__device__ float g_Y[(size_t)NN * BB * BB];    // 128 MB (Y fp32, then SM tf32-rounded)
__device__ float g_Xt[(size_t)NN * CC * BB];   // 64 MB (X tf32-rounded)
__device__ float g_Wkt[CC * CC];               // 4 MB
__device__ float g_Wqt[CC * CC];               // 4 MB
__device__ float g_DK2[NN * BB];
__device__ float g_DQ2[NN * BB];

__device__ __forceinline__ uint32_t f2tf(float f) {
    uint32_t r;
    asm volatile("cvt.rna.tf32.f32 %0, %1;" : "=r"(r) : "f"(f));
    return r;
}
__device__ __forceinline__ float roundtf(float f) { return __uint_as_float(f2tf(f)); }

__device__ __forceinline__ void cp16(float* smem, const float* g) {
    uint32_t s = (uint32_t)__cvta_generic_to_shared(smem);
    asm volatile("cp.async.cg.shared.global [%0], [%1], 16;" :: "r"(s), "l"(g));
}
__device__ __forceinline__ void cp_commit() {
    asm volatile("cp.async.commit_group;");
}

__device__ __forceinline__ void mma_tf32(float (&d)[4], const uint32_t (&a)[4],
                                         const uint32_t (&b)[2]) {
    asm volatile(
        "mma.sync.aligned.m16n8k8.row.col.f32.tf32.tf32.f32 "
        "{%0,%1,%2,%3}, {%4,%5,%6,%7}, {%8,%9}, {%0,%1,%2,%3};"
        : "+f"(d[0]), "+f"(d[1]), "+f"(d[2]), "+f"(d[3])
        : "r"(a[0]), "r"(a[1]), "r"(a[2]), "r"(a[3]),
          "r"(b[0]), "r"(b[1]));
}

// ===========================================================================
// TF32 warp-MMA GEMM: CTA tile 128x256, BK=16, 8 warps (2m x 4n), warp 64x64,
// 3-stage cp.async pipeline. All operands pre-rounded to TF32 in gmem, so the
// inner loop is pure LDS + HMMA (no cvt).
// MODE: 0 = proj (C = A@B + bias, output tf32-rounded),
//       1 = score (C = A^T@B * rsqrt(dq*dk), output fp32),
//       2 = mix   (C = A@B, output fp32)
// AKM:  A tile stored k-major (A column-major in gmem: elem(m,k)=A[k*lda+m])
// ===========================================================================
#define BM 128
#define BN 256
#define BK 16

template <int MODE, int KDIM, bool AKM>
__global__ __launch_bounds__(256, 1)
void gemm_tf32(const float* __restrict__ A, int lda, size_t strA,
               const float* __restrict__ B, int ldb, size_t strB,
               float* __restrict__ C, int ldc, size_t strC,
               const float* __restrict__ bias,
               const float* __restrict__ dq2_all,
               const float* __restrict__ dk2_all)
{
    constexpr int SA_STRIDE = AKM ? 136 : 20;     // km: [16][128+8]; rm: [128][16+4]
    constexpr int SA_SZ = AKM ? 16 * 136 : 128 * 20;
    constexpr int SB_STRIDE = 264;                // [16][256+8]
    constexpr int SB_SZ = 16 * SB_STRIDE;
    constexpr int STAGE = SA_SZ + SB_SZ;
    extern __shared__ float smem[];

    const int n = blockIdx.z;
    const float* An = A + (size_t)n * strA;
    const float* Bn = B + (size_t)n * strB;
    float* Cn = C + (size_t)n * strC;

    const int row0 = blockIdx.y * BM;
    const int col0 = blockIdx.x * BN;

    const int tid = threadIdx.x;
    const int lane = tid & 31;
    const int warp = tid >> 5;
    const int wm = warp >> 2;   // 0..1 (64-row slab)
    const int wn = warp & 3;    // 0..3 (64-col slab)
    const int lr = lane >> 2;   // 0..7
    const int lc = lane & 3;    // 0..3

    float acc[4][8][4] = {};

    auto loadA = [&](float* s, int k0) {
        if (!AKM) {
            #pragma unroll
            for (int i = tid; i < 512; i += 256) {
                int r = i >> 2, sg = i & 3;
                cp16(s + r * 20 + sg * 4,
                     An + (size_t)(row0 + r) * lda + k0 + sg * 4);
            }
        } else {
            #pragma unroll
            for (int i = tid; i < 512; i += 256) {
                int r = i >> 5, sg = i & 31;
                cp16(s + r * 136 + sg * 4,
                     An + (size_t)(k0 + r) * lda + row0 + sg * 4);
            }
        }
    };
    auto loadB = [&](float* s, int k0) {
        #pragma unroll
        for (int i = tid; i < 1024; i += 256) {
            int r = i >> 6, sg = i & 63;
            cp16(s + r * SB_STRIDE + sg * 4,
                 Bn + (size_t)(k0 + r) * ldb + col0 + sg * 4);
        }
    };

    constexpr int KTILES = KDIM / BK;

    // prologue: stages 0 and 1 in flight
    loadA(smem, 0);
    loadB(smem + SA_SZ, 0);
    cp_commit();
    loadA(smem + STAGE, BK);
    loadB(smem + STAGE + SA_SZ, BK);
    cp_commit();

    for (int kt = 0; kt < KTILES; kt++) {
        if (kt < KTILES - 1) {
            asm volatile("cp.async.wait_group 1;");
        } else {
            asm volatile("cp.async.wait_group 0;");
        }
        __syncthreads();

        // issue loads for stage kt+2 into buffer (kt+2)%3 (free since kt-1 done)
        if (kt + 2 < KTILES) {
            float* s = smem + ((kt + 2) % 3) * STAGE;
            loadA(s, (kt + 2) * BK);
            loadB(s + SA_SZ, (kt + 2) * BK);
            cp_commit();
        }

        const float* cA = smem + (kt % 3) * STAGE;
        const float* cB = cA + SA_SZ;

        #pragma unroll
        for (int ks = 0; ks < 2; ks++) {
            const int kb = ks * 8;
            uint32_t af[4][4];
            uint32_t bf[8][2];

            #pragma unroll
            for (int mi = 0; mi < 4; mi++) {
                const int r = wm * 64 + mi * 16 + lr;
                const int c = kb + lc;
                if (!AKM) {
                    af[mi][0] = __float_as_uint(cA[r * 20 + c]);
                    af[mi][1] = __float_as_uint(cA[(r + 8) * 20 + c]);
                    af[mi][2] = __float_as_uint(cA[r * 20 + c + 4]);
                    af[mi][3] = __float_as_uint(cA[(r + 8) * 20 + c + 4]);
                } else {
                    af[mi][0] = __float_as_uint(cA[c * 136 + r]);
                    af[mi][1] = __float_as_uint(cA[c * 136 + r + 8]);
                    af[mi][2] = __float_as_uint(cA[(c + 4) * 136 + r]);
                    af[mi][3] = __float_as_uint(cA[(c + 4) * 136 + r + 8]);
                }
            }
            #pragma unroll
            for (int ni = 0; ni < 8; ni++) {
                const int kr = kb + lc;
                const int nc = wn * 64 + ni * 8 + lr;
                bf[ni][0] = __float_as_uint(cB[kr * SB_STRIDE + nc]);
                bf[ni][1] = __float_as_uint(cB[(kr + 4) * SB_STRIDE + nc]);
            }
            #pragma unroll
            for (int mi = 0; mi < 4; mi++)
                #pragma unroll
                for (int ni = 0; ni < 8; ni++)
                    mma_tf32(acc[mi][ni], af[mi], bf[ni]);
        }
        __syncthreads();
    }

    // ---- epilogue ----
    const float* dq2 = (MODE == 1) ? dq2_all + n * BB : nullptr;
    const float* dk2 = (MODE == 1) ? dk2_all + n * BB : nullptr;

    #pragma unroll
    for (int mi = 0; mi < 4; mi++) {
        const int m = row0 + wm * 64 + mi * 16 + lr;
        float b0 = 0.f, b1 = 0.f, dq0 = 0.f, dq1 = 0.f;
        if (MODE == 0) { b0 = bias[m]; b1 = bias[m + 8]; }
        if (MODE == 1) { dq0 = dq2[m]; dq1 = dq2[m + 8]; }

        #pragma unroll
        for (int ni = 0; ni < 8; ni++) {
            const int nn = col0 + wn * 64 + ni * 8 + 2 * lc;
            float v00 = acc[mi][ni][0], v01 = acc[mi][ni][1];
            float v10 = acc[mi][ni][2], v11 = acc[mi][ni][3];
            if (MODE == 0) {
                // output feeds the score GEMM -> round to tf32 now
                v00 = roundtf(v00 + b0); v01 = roundtf(v01 + b0);
                v10 = roundtf(v10 + b1); v11 = roundtf(v11 + b1);
            } else if (MODE == 1) {
                float dk0 = dk2[nn], dk1 = dk2[nn + 1];
                v00 *= rsqrtf(fmaxf(dq0 * dk0, EPS));
                v01 *= rsqrtf(fmaxf(dq0 * dk1, EPS));
                v10 *= rsqrtf(fmaxf(dq1 * dk0, EPS));
                v11 *= rsqrtf(fmaxf(dq1 * dk1, EPS));
            }
            *reinterpret_cast<float2*>(&Cn[(size_t)m * ldc + nn]) = make_float2(v00, v01);
            *reinterpret_cast<float2*>(&Cn[(size_t)(m + 8) * ldc + nn]) = make_float2(v10, v11);
        }
    }
}

// ---------------------------------------------------------------------------
// Elementwise: round fp32 -> tf32-valued fp32 (vectorized)
// ---------------------------------------------------------------------------
__global__ __launch_bounds__(256)
void tf32_round_kernel(const float* __restrict__ in, float* __restrict__ out, int n4)
{
    int i = blockIdx.x * 256 + threadIdx.x;
    int stride = gridDim.x * 256;
    for (; i < n4; i += stride) {
        float4 v = reinterpret_cast<const float4*>(in)[i];
        v.x = roundtf(v.x); v.y = roundtf(v.y);
        v.z = roundtf(v.z); v.w = roundtf(v.w);
        reinterpret_cast<float4*>(out)[i] = v;
    }
}

// ---------------------------------------------------------------------------
// Column squared norms of K and Q (operate on tf32-rounded values — matches
// exactly what the score MMA consumes)
// ---------------------------------------------------------------------------
__global__ __launch_bounds__(256)
void sq_kernel()
{
    int idx = blockIdx.x * 256 + threadIdx.x;
    int n = idx / BB;
    int b = idx % BB;
    const float* Kn = g_K + (size_t)n * CC * BB + b;
    const float* Qn = g_Q + (size_t)n * CC * BB + b;
    float sk = 0.f, sq = 0.f;
    #pragma unroll 4
    for (int c = 0; c < CC; c++) {
        float kv = Kn[(size_t)c * BB];
        float qv = Qn[(size_t)c * BB];
        sk = fmaf(kv, kv, sk);
        sq = fmaf(qv, qv, sq);
    }
    g_DK2[idx] = sk;
    g_DQ2[idx] = sq;
}

// ---------------------------------------------------------------------------
// Softmax over b (axis=1) of Y[n,b,k], in place; final write tf32-rounded
// (feeds the mix GEMM directly).
// ---------------------------------------------------------------------------
__global__ __launch_bounds__(256)
void softmax_kernel()
{
    const int n = blockIdx.y;
    const int k = blockIdx.x * 256 + threadIdx.x;
    float* Yn = g_Y + (size_t)n * BB * BB + k;

    float m = -INFINITY;
    #pragma unroll 4
    for (int b = 0; b < BB; b++)
        m = fmaxf(m, Yn[(size_t)b * BB]);

    float s = 0.f;
    #pragma unroll 4
    for (int b = 0; b < BB; b++) {
        float e = expf(Yn[(size_t)b * BB] - m);
        s += e;
        Yn[(size_t)b * BB] = e;
    }

    float inv = 1.f / s;
    #pragma unroll 4
    for (int b = 0; b < BB; b++)
        Yn[(size_t)b * BB] = roundtf(Yn[(size_t)b * BB] * inv);
}

// ---------------------------------------------------------------------------
extern "C" void kernel_launch(void* const* d_in, const int* in_sizes, int n_in,
                              void* d_out, int out_size)
{
    const float* X    = (const float*)d_in[0];
    const float* Wk_w = (const float*)d_in[1];
    const float* Wk_b = (const float*)d_in[2];
    const float* Wq_w = (const float*)d_in[3];
    const float* Wq_b = (const float*)d_in[4];
    float* Z = (float*)d_out;

    float* Kd;  cudaGetSymbolAddress((void**)&Kd,  g_K);
    float* Qd;  cudaGetSymbolAddress((void**)&Qd,  g_Q);
    float* Yd;  cudaGetSymbolAddress((void**)&Yd,  g_Y);
    float* Xt;  cudaGetSymbolAddress((void**)&Xt,  g_Xt);
    float* Wkt; cudaGetSymbolAddress((void**)&Wkt, g_Wkt);
    float* Wqt; cudaGetSymbolAddress((void**)&Wqt, g_Wqt);
    float* DK2; cudaGetSymbolAddress((void**)&DK2, g_DK2);
    float* DQ2; cudaGetSymbolAddress((void**)&DQ2, g_DQ2);

    const size_t sXn = (size_t)CC * BB;
    const size_t sYn = (size_t)BB * BB;

    // dynamic smem sizes per instantiation (3 stages)
    constexpr int SB_SZ = 16 * 264;
    constexpr size_t smem_rm = 3 * (size_t)(128 * 20 + SB_SZ) * 4;  // ~81.4 KB
    constexpr size_t smem_km = 3 * (size_t)(16 * 136 + SB_SZ) * 4;  // ~76.8 KB

    static bool attr_done = false;
    if (!attr_done) {
        cudaFuncSetAttribute(gemm_tf32<0, CC, false>,
                             cudaFuncAttributeMaxDynamicSharedMemorySize, (int)smem_rm);
        cudaFuncSetAttribute(gemm_tf32<1, CC, true>,
                             cudaFuncAttributeMaxDynamicSharedMemorySize, (int)smem_km);
        cudaFuncSetAttribute(gemm_tf32<2, BB, false>,
                             cudaFuncAttributeMaxDynamicSharedMemorySize, (int)smem_rm);
        attr_done = true;
    }

    // 0) pre-round operands to tf32
    tf32_round_kernel<<<1024, 256>>>(X, Xt, (int)(NN * sXn / 4));
    tf32_round_kernel<<<256, 256>>>(Wk_w, Wkt, CC * CC / 4);
    tf32_round_kernel<<<256, 256>>>(Wq_w, Wqt, CC * CC / 4);

    // 1) projections (outputs tf32-rounded)
    gemm_tf32<0, CC, false><<<dim3(BB / BN, CC / BM, NN), 256, smem_rm>>>(
        Wkt, CC, 0, Xt, BB, sXn, Kd, BB, sXn, Wk_b, nullptr, nullptr);
    gemm_tf32<0, CC, false><<<dim3(BB / BN, CC / BM, NN), 256, smem_rm>>>(
        Wqt, CC, 0, Xt, BB, sXn, Qd, BB, sXn, Wq_b, nullptr, nullptr);

    // 2) squared norms
    sq_kernel<<<(NN * BB) / 256, 256>>>();

    // 3) normalized scores: Y = Q^T @ K * rsqrt(DQ2⊗DK2)
    gemm_tf32<1, CC, true><<<dim3(BB / BN, BB / BM, NN), 256, smem_km>>>(
        Qd, BB, sXn, Kd, BB, sXn, Yd, BB, sYn, nullptr, DQ2, DK2);

    // 4) softmax over query axis (in place; output tf32-rounded)
    softmax_kernel<<<dim3(BB / 256, NN), 256>>>();

    // 5) output mix: Z = X @ SM
    gemm_tf32<2, BB, false><<<dim3(BB / BN, CC / BM, NN), 256, smem_rm>>>(
        Xt, BB, sXn, Yd, BB, sYn, Z, BB, sXn, nullptr, nullptr, nullptr);
}